// round 12
// baseline (speedup 1.0000x reference)
#include <cuda_runtime.h>
#include <cuda_bf16.h>
#include <cstdint>
#include <math.h>

// ===========================================================================
// WindowAttentionV2: split-bf16 mma.sync; fused attention+proj; packed qkv.
// B=2048 win, N=64 tok, C=256, H=8, D=32.
// ===========================================================================

// ---- device scratch --------------------------------------------------------
__device__ uint32_t g_qkv[3u * 2048 * 8 * 2048];       // packed bf16 (hi|lo<<16)
__device__ __nv_bfloat16 g_xhi[131072u * 256];
__device__ __nv_bfloat16 g_xlo[131072u * 256];
__device__ __nv_bfloat16 g_wqkv_hi[768 * 256];         // [n][k]
__device__ __nv_bfloat16 g_wqkv_lo[768 * 256];
__device__ __nv_bfloat16 g_wproj_hi[256 * 256];
__device__ __nv_bfloat16 g_wproj_lo[256 * 256];
__device__ float g_rel_bias[8 * 64 * 64];
__device__ float g_bias_qkv[768];

// ---- helpers ----------------------------------------------------------------
__device__ __forceinline__ uint32_t smem_u32(const void* p) {
    uint32_t a;
    asm("{ .reg .u64 t; cvta.to.shared.u64 t, %1; cvt.u32.u64 %0, t; }"
        : "=r"(a) : "l"(p));
    return a;
}
__device__ __forceinline__ void mma_bf16(float* c, const uint32_t* a, const uint32_t* b) {
    asm volatile(
        "mma.sync.aligned.m16n8k16.row.col.f32.bf16.bf16.f32 "
        "{%0,%1,%2,%3}, {%4,%5,%6,%7}, {%8,%9}, {%0,%1,%2,%3};"
        : "+f"(c[0]), "+f"(c[1]), "+f"(c[2]), "+f"(c[3])
        : "r"(a[0]), "r"(a[1]), "r"(a[2]), "r"(a[3]), "r"(b[0]), "r"(b[1]));
}
__device__ __forceinline__ void ldm4(uint32_t* r, uint32_t addr) {
    asm volatile("ldmatrix.sync.aligned.m8n8.x4.shared.b16 {%0,%1,%2,%3}, [%4];"
                 : "=r"(r[0]), "=r"(r[1]), "=r"(r[2]), "=r"(r[3]) : "r"(addr));
}
__device__ __forceinline__ void cpasync16(uint32_t dst, const void* src) {
    asm volatile("cp.async.cg.shared.global [%0], [%1], 16;" :: "r"(dst), "l"(src));
}
__device__ __forceinline__ void bf_split(float v, __nv_bfloat16& hi, __nv_bfloat16& lo) {
    hi = __float2bfloat16(v);
    lo = __float2bfloat16(v - __bfloat162float(hi));
}
__device__ __forceinline__ uint32_t pack_bf(__nv_bfloat16 a, __nv_bfloat16 b) {
    return (uint32_t)__bfloat16_as_ushort(a) | ((uint32_t)__bfloat16_as_ushort(b) << 16);
}
__device__ __forceinline__ uint32_t pack_hi2(float a, float b) {
    return pack_bf(__float2bfloat16(a), __float2bfloat16(b));
}
__device__ __forceinline__ uint32_t pack_lo2(float a, float b) {
    __nv_bfloat16 ha = __float2bfloat16(a), hb = __float2bfloat16(b);
    return pack_bf(__float2bfloat16(a - __bfloat162float(ha)),
                   __float2bfloat16(b - __bfloat162float(hb)));
}
// packed qkv element: low16 = hi, high16 = lo
__device__ __forceinline__ uint32_t enc_hl(float v) {
    __nv_bfloat16 h, l;
    bf_split(v, h, l);
    return pack_bf(h, l);
}
__device__ __forceinline__ float dec_hl(uint32_t u) {
    return __bfloat162float(__ushort_as_bfloat16((unsigned short)(u & 0xffffu)))
         + __bfloat162float(__ushort_as_bfloat16((unsigned short)(u >> 16)));
}

// ===========================================================================
// prep_x: x fp32 -> bf16 hi/lo
// ===========================================================================
__global__ void prep_x_kernel(const float* __restrict__ x)
{
    int gid = blockIdx.x * blockDim.x + threadIdx.x;
    int gsz = gridDim.x * blockDim.x;
    for (int i = gid; i < 131072 * 64; i += gsz) {
        float4 f = ((const float4*)x)[i];
        __nv_bfloat16 h0, h1, h2, h3, l0, l1, l2, l3;
        bf_split(f.x, h0, l0); bf_split(f.y, h1, l1);
        bf_split(f.z, h2, l2); bf_split(f.w, h3, l3);
        ((__nv_bfloat162*)g_xhi)[2 * i]     = __nv_bfloat162(h0, h1);
        ((__nv_bfloat162*)g_xhi)[2 * i + 1] = __nv_bfloat162(h2, h3);
        ((__nv_bfloat162*)g_xlo)[2 * i]     = __nv_bfloat162(l0, l1);
        ((__nv_bfloat162*)g_xlo)[2 * i + 1] = __nv_bfloat162(l2, l3);
    }
}

// ===========================================================================
// prep_w: weights -> [n][k] bf16 hi/lo, qkv bias pack
// ===========================================================================
__global__ void prep_w_kernel(const float* __restrict__ qkv_w,
                              const float* __restrict__ proj_w,
                              const float* __restrict__ q_bias,
                              const float* __restrict__ v_bias)
{
    int gid = blockIdx.x * blockDim.x + threadIdx.x;
    int gsz = gridDim.x * blockDim.x;
    for (int i = gid; i < 768 * 256; i += gsz) {
        int n = i >> 8, k = i & 255;
        __nv_bfloat16 hi, lo;
        bf_split(qkv_w[(size_t)k * 768 + n], hi, lo);
        g_wqkv_hi[i] = hi; g_wqkv_lo[i] = lo;
    }
    for (int i = gid; i < 256 * 256; i += gsz) {
        int n = i >> 8, k = i & 255;
        __nv_bfloat16 hi, lo;
        bf_split(proj_w[(size_t)k * 256 + n], hi, lo);
        g_wproj_hi[i] = hi; g_wproj_lo[i] = lo;
    }
    for (int i = gid; i < 768; i += gsz)
        g_bias_qkv[i] = (i < 256) ? q_bias[i] : ((i < 512) ? 0.f : v_bias[i - 512]);
}

// ===========================================================================
// cpb: continuous position bias (window-independent)
// ===========================================================================
__global__ void cpb_kernel(const float* __restrict__ coords_table,
                           const float* __restrict__ mlp1_w,
                           const float* __restrict__ mlp1_b,
                           const float* __restrict__ mlp2_w,
                           const int*   __restrict__ rel_pos_index)
{
    __shared__ float bt[225 * 8];
    int t = threadIdx.x;
    if (t < 225) {
        float c0 = coords_table[t * 2 + 0];
        float c1 = coords_table[t * 2 + 1];
        float acc[8];
#pragma unroll
        for (int hh = 0; hh < 8; hh++) acc[hh] = 0.f;
        for (int k = 0; k < 512; k++) {
            float hv = fmaxf(c0 * mlp1_w[k] + c1 * mlp1_w[512 + k] + mlp1_b[k], 0.f);
#pragma unroll
            for (int hh = 0; hh < 8; hh++) acc[hh] += hv * mlp2_w[k * 8 + hh];
        }
#pragma unroll
        for (int hh = 0; hh < 8; hh++) bt[t * 8 + hh] = acc[hh];
    }
    __syncthreads();
    for (int idx = t; idx < 8 * 64 * 64; idx += blockDim.x) {
        int hh = idx >> 12;
        int ij = idx & 4095;
        float v = bt[rel_pos_index[ij] * 8 + hh];
        g_rel_bias[idx] = 16.f / (1.f + __expf(-v));
    }
}

// ===========================================================================
// gemm_qkv: C[128,256] CTA tile (ntile = qkv section), split bf16.
// k32 double-buffered cp.async pipeline. 8 warps (4m x 2n), warp tile 32x128.
// grid (3, 1024). occ 1 (120KB smem, ~190 regs).
// ===========================================================================
#define LDC 40
#define A_CH (128 * LDC * 2)          // 10240 per polarity
#define B_CH (256 * LDC * 2)          // 20480 per polarity
#define BUF_B (2 * A_CH + 2 * B_CH)   // AH AL BH BL = 61440
#define SMEM_G (2 * BUF_B)            // 122880

__global__ void __launch_bounds__(256, 1)
gemm_qkv_kernel()
{
    extern __shared__ __nv_bfloat16 smb[];
    const uint32_t sb = smem_u32(smb);

    const int t = threadIdx.x, lane = t & 31, w = t >> 5;
    const int wm = w & 3, wn = w >> 2;
    const int ntile = blockIdx.x, mtile = blockIdx.y;   // ntile = qkv section

    const size_t aoff = (size_t)mtile * 128 * 256;
    const size_t boff = (size_t)ntile * 256 * 256;

    auto stage = [&](int s, int buf) {
        const int k0 = s * 32;
        const uint32_t AH = sb + buf * BUF_B;
        const uint32_t AL = AH + A_CH;
        const uint32_t BH = AL + A_CH;
        const uint32_t BL = BH + B_CH;
        // A: 128 rows x 32 cols = 512 x 16B per polarity
#pragma unroll
        for (int rep = 0; rep < 2; rep++) {
            int idx = rep * 256 + t;
            int row = idx >> 2, cg = idx & 3;
            uint32_t so = (uint32_t)(row * LDC + cg * 8) * 2;
            size_t go = (size_t)row * 256 + k0 + cg * 8;
            cpasync16(AH + so, g_xhi + aoff + go);
            cpasync16(AL + so, g_xlo + aoff + go);
        }
        // B: 256 rows x 32 cols = 1024 x 16B per polarity
#pragma unroll
        for (int rep = 0; rep < 4; rep++) {
            int idx = rep * 256 + t;
            int row = idx >> 2, cg = idx & 3;
            uint32_t so = (uint32_t)(row * LDC + cg * 8) * 2;
            size_t go = boff + (size_t)row * 256 + k0 + cg * 8;
            cpasync16(BH + so, g_wqkv_hi + go);
            cpasync16(BL + so, g_wqkv_lo + go);
        }
        asm volatile("cp.async.commit_group;" ::: "memory");
    };

    float acc[2][16][4];
#pragma unroll
    for (int mi = 0; mi < 2; mi++)
#pragma unroll
        for (int n8 = 0; n8 < 16; n8++)
#pragma unroll
            for (int r = 0; r < 4; r++) acc[mi][n8][r] = 0.f;

    stage(0, 0);
    stage(1, 1);

    for (int s = 0; s < 8; s++) {
        if (s < 7) asm volatile("cp.async.wait_group 1;" ::: "memory");
        else       asm volatile("cp.async.wait_group 0;" ::: "memory");
        __syncthreads();

        const uint32_t AH = sb + (s & 1) * BUF_B;
        const uint32_t AL = AH + A_CH;
        const uint32_t BH = AL + A_CH;
        const uint32_t BL = BH + B_CH;

#pragma unroll
        for (int ks = 0; ks < 2; ks++) {
            uint32_t ah[2][4], al[2][4];
            {
                int arow = wm * 32 + (lane & 15);
                int acol = ks * 16 + ((lane >> 4) << 3);
                uint32_t ao = (uint32_t)(arow * LDC + acol) * 2;
                ldm4(ah[0], AH + ao);
                ldm4(ah[1], AH + ao + 16 * LDC * 2);
                ldm4(al[0], AL + ao);
                ldm4(al[1], AL + ao + 16 * LDC * 2);
            }
            const int quad = lane >> 3, l8 = lane & 7;
            const int bcol = ks * 16 + ((quad & 1) << 3);
#pragma unroll
            for (int np = 0; np < 8; np++) {
                int brow = wn * 128 + np * 16 + ((quad >> 1) << 3) + l8;
                uint32_t bo = (uint32_t)(brow * LDC + bcol) * 2;
                uint32_t bq[4];
                ldm4(bq, BH + bo);
#pragma unroll
                for (int mi = 0; mi < 2; mi++) {
                    mma_bf16(acc[mi][2 * np + 0], ah[mi], bq + 0);   // hi*whi
                    mma_bf16(acc[mi][2 * np + 1], ah[mi], bq + 2);
                    mma_bf16(acc[mi][2 * np + 0], al[mi], bq + 0);   // lo*whi
                    mma_bf16(acc[mi][2 * np + 1], al[mi], bq + 2);
                }
                ldm4(bq, BL + bo);
#pragma unroll
                for (int mi = 0; mi < 2; mi++) {
                    mma_bf16(acc[mi][2 * np + 0], ah[mi], bq + 0);   // hi*wlo
                    mma_bf16(acc[mi][2 * np + 1], ah[mi], bq + 2);
                }
            }
        }
        __syncthreads();
        if (s + 2 < 8) stage(s + 2, s & 1);
    }

    // ---- epilogue: packed bf16 hi/lo scatter to g_qkv + bias --------------------
    const int row_l = wm * 32 + (lane >> 2);
    const int col_l2 = (lane & 3) * 2;
#pragma unroll
    for (int mi = 0; mi < 2; mi++) {
#pragma unroll
        for (int n8 = 0; n8 < 16; n8++) {
            int gc = ntile * 256 + wn * 128 + n8 * 8 + col_l2;
            int sec = gc >> 8, hh = (gc >> 5) & 7, d = gc & 31;
            float b0 = g_bias_qkv[gc], b1 = g_bias_qkv[gc + 1];
#pragma unroll
            for (int half = 0; half < 2; half++) {
                int row = mtile * 128 + row_l + mi * 16 + half * 8;
                int win = row >> 6, tok = row & 63;
                size_t addr = (((size_t)sec * 2048 + win) * 8 + hh) * 2048
                              + (size_t)tok * 32 + d;
                uint2 pv;
                pv.x = enc_hl(acc[mi][n8][2 * half + 0] + b0);
                pv.y = enc_hl(acc[mi][n8][2 * half + 1] + b1);
                *(uint2*)&g_qkv[addr] = pv;
            }
        }
    }
}

// ===========================================================================
// attnproj: fused attention + proj. CTA = window, 256 thr = 2 groups x 4 warps.
// qkv read packed bf16 hi/lo. ctx in registers; proj in 4 n64 passes with
// staging hidden under reduction barriers.
// ===========================================================================
#define LQ 40    // q/k hi/lo row stride (bf16)
#define LV 72    // VT row stride (bf16)
#define LWB 136  // proj B stage row stride (bf16): 272B % 128 == 16
#define LRED 68  // RED row stride (fp32)

#define GRP_BYTES 29696   // per-group attn scratch (QH QL KH KL VTH VTL)
#define WB_GRP 34816      // per-group proj WB (hi 17408 + lo 17408), n64
#define SM_TOTAL 87040    // max(2*GRP_BYTES=59392, 2*WB_GRP + RED 17408 = 87040)

__global__ void __launch_bounds__(256, 2)
attnproj_kernel(const float* __restrict__ mask,
                const float* __restrict__ logit_scale,
                const float* __restrict__ proj_b,
                float*       __restrict__ out)
{
    __shared__ __align__(16) char smraw[SM_TOTAL];
    const uint32_t sb = smem_u32(smraw);

    const int t = threadIdx.x, lane = t & 31, w = t >> 5;
    const int g = w >> 2, wm = w & 3, tg = t & 127;
    const int win = blockIdx.x;
    const int quad = lane >> 3, l8 = lane & 7;

    const uint32_t gb = sb + g * GRP_BYTES;
    const uint32_t uQH = gb, uQL = gb + 5120, uKH = gb + 10240, uKL = gb + 15360;
    const uint32_t uVH = gb + 20480, uVL = gb + 25088;
    __nv_bfloat16* VTH = (__nv_bfloat16*)(smraw + g * GRP_BYTES + 20480);
    __nv_bfloat16* VTL = (__nv_bfloat16*)(smraw + g * GRP_BYTES + 25088);

    // ctx register file: [head-it][k16-frag kf][4 regs], hi and lo
    uint32_t cxh[4][8], cxl[4][8];

    // =================== attention: 4 heads per group =========================
    for (int it = 0; it < 4; it++) {
        const int h = g * 4 + it;
        const uint32_t* qg = g_qkv + (((size_t)0 * 2048 + win) * 8 + h) * 2048;
        const uint32_t* kg = g_qkv + (((size_t)1 * 2048 + win) * 8 + h) * 2048;
        const uint32_t* vg = g_qkv + (((size_t)2 * 2048 + win) * 8 + h) * 2048;

        // V (packed) -> VT hi/lo (transposed)
#pragma unroll
        for (int rep = 0; rep < 4; rep++) {
            int idx = rep * 128 + tg;           // 0..511 uint4
            int tok = idx >> 3, d4 = (idx & 7) * 4;
            uint4 fv = ((const uint4*)vg)[idx];
            uint32_t u[4] = {fv.x, fv.y, fv.z, fv.w};
#pragma unroll
            for (int j = 0; j < 4; j++) {
                VTH[(d4 + j) * LV + tok] = __ushort_as_bfloat16((unsigned short)(u[j] & 0xffffu));
                VTL[(d4 + j) * LV + tok] = __ushort_as_bfloat16((unsigned short)(u[j] >> 16));
            }
        }

        // q/k per-thread row normalize (decode packed) -> hi/lo in smem
        {
            int r = tg & 63;
            const uint32_t* src = (tg < 64) ? (qg + r * 32) : (kg + r * 32);
            float rv[32];
            float s = 0.f;
#pragma unroll
            for (int i = 0; i < 8; i++) {
                uint4 u = ((const uint4*)src)[i];
                rv[4 * i + 0] = dec_hl(u.x);
                rv[4 * i + 1] = dec_hl(u.y);
                rv[4 * i + 2] = dec_hl(u.z);
                rv[4 * i + 3] = dec_hl(u.w);
                s += rv[4 * i + 0] * rv[4 * i + 0] + rv[4 * i + 1] * rv[4 * i + 1]
                   + rv[4 * i + 2] * rv[4 * i + 2] + rv[4 * i + 3] * rv[4 * i + 3];
            }
            float inv = rsqrtf(fmaxf(s, 1e-24f));
            if (tg < 64) inv *= __expf(fminf(logit_scale[h], 4.605170185988092f));
            uint32_t dh = ((tg < 64) ? uQH : uKH) + (uint32_t)(r * LQ) * 2;
            uint32_t dl = ((tg < 64) ? uQL : uKL) + (uint32_t)(r * LQ) * 2;
#pragma unroll
            for (int i = 0; i < 8; i++) {
                float v0 = rv[4 * i + 0] * inv, v1 = rv[4 * i + 1] * inv;
                float v2 = rv[4 * i + 2] * inv, v3 = rv[4 * i + 3] * inv;
                asm volatile("st.shared.v2.b32 [%0], {%1,%2};"
                             :: "r"(dh + i * 8), "r"(pack_hi2(v0, v1)), "r"(pack_hi2(v2, v3)));
                asm volatile("st.shared.v2.b32 [%0], {%1,%2};"
                             :: "r"(dl + i * 8), "r"(pack_lo2(v0, v1)), "r"(pack_lo2(v2, v3)));
            }
        }
        asm volatile("bar.sync %0, 128;" :: "r"(g + 1) : "memory");

        // QK^T: warp wm -> rows m16, n=64
        float acc[8][4];
#pragma unroll
        for (int n8 = 0; n8 < 8; n8++)
#pragma unroll
            for (int r = 0; r < 4; r++) acc[n8][r] = 0.f;

#pragma unroll
        for (int ks = 0; ks < 2; ks++) {
            uint32_t ah[4], al[4];
            {
                int arow = wm * 16 + (lane & 15);
                int acol = ks * 16 + ((lane >> 4) << 3);
                uint32_t ao = (uint32_t)(arow * LQ + acol) * 2;
                ldm4(ah, uQH + ao);
                ldm4(al, uQL + ao);
            }
            const int bcol = ks * 16 + ((quad & 1) << 3);
#pragma unroll
            for (int np = 0; np < 4; np++) {
                int brow = np * 16 + ((quad >> 1) << 3) + l8;
                uint32_t bo = (uint32_t)(brow * LQ + bcol) * 2;
                uint32_t bq[4];
                ldm4(bq, uKH + bo);
                mma_bf16(acc[2 * np + 0], ah, bq + 0);
                mma_bf16(acc[2 * np + 1], ah, bq + 2);
                mma_bf16(acc[2 * np + 0], al, bq + 0);
                mma_bf16(acc[2 * np + 1], al, bq + 2);
                ldm4(bq, uKL + bo);
                mma_bf16(acc[2 * np + 0], ah, bq + 0);
                mma_bf16(acc[2 * np + 1], ah, bq + 2);
            }
        }

        // + rel_bias + mask, softmax on fragments
        {
            const float* rb = g_rel_bias + h * 4096;
            const float* mk = mask + (size_t)(win & 255) * 4096;
            const int i0 = wm * 16 + (lane >> 2);
            const int i1 = i0 + 8;
            const int jc = (lane & 3) * 2;
#pragma unroll
            for (int n8 = 0; n8 < 8; n8++) {
                int o0 = i0 * 64 + n8 * 8 + jc;
                int o1 = i1 * 64 + n8 * 8 + jc;
                float2 r0 = *(const float2*)(rb + o0), m0 = *(const float2*)(mk + o0);
                float2 r1 = *(const float2*)(rb + o1), m1 = *(const float2*)(mk + o1);
                acc[n8][0] += r0.x + m0.x;  acc[n8][1] += r0.y + m0.y;
                acc[n8][2] += r1.x + m1.x;  acc[n8][3] += r1.y + m1.y;
            }
            float mx0 = -1e30f, mx1 = -1e30f;
#pragma unroll
            for (int n8 = 0; n8 < 8; n8++) {
                mx0 = fmaxf(mx0, fmaxf(acc[n8][0], acc[n8][1]));
                mx1 = fmaxf(mx1, fmaxf(acc[n8][2], acc[n8][3]));
            }
            mx0 = fmaxf(mx0, __shfl_xor_sync(0xffffffffu, mx0, 1));
            mx0 = fmaxf(mx0, __shfl_xor_sync(0xffffffffu, mx0, 2));
            mx1 = fmaxf(mx1, __shfl_xor_sync(0xffffffffu, mx1, 1));
            mx1 = fmaxf(mx1, __shfl_xor_sync(0xffffffffu, mx1, 2));
            float s0 = 0.f, s1 = 0.f;
#pragma unroll
            for (int n8 = 0; n8 < 8; n8++) {
                acc[n8][0] = __expf(acc[n8][0] - mx0);
                acc[n8][1] = __expf(acc[n8][1] - mx0);
                acc[n8][2] = __expf(acc[n8][2] - mx1);
                acc[n8][3] = __expf(acc[n8][3] - mx1);
                s0 += acc[n8][0] + acc[n8][1];
                s1 += acc[n8][2] + acc[n8][3];
            }
            s0 += __shfl_xor_sync(0xffffffffu, s0, 1);
            s0 += __shfl_xor_sync(0xffffffffu, s0, 2);
            s1 += __shfl_xor_sync(0xffffffffu, s1, 1);
            s1 += __shfl_xor_sync(0xffffffffu, s1, 2);
            float inv0 = 1.f / s0, inv1 = 1.f / s1;
#pragma unroll
            for (int n8 = 0; n8 < 8; n8++) {
                acc[n8][0] *= inv0;  acc[n8][1] *= inv0;
                acc[n8][2] *= inv1;  acc[n8][3] *= inv1;
            }
        }

        // PV with register P fragments -> acc2 (m16 x d32)
        float acc2[4][4];
#pragma unroll
        for (int n8 = 0; n8 < 4; n8++)
#pragma unroll
            for (int r = 0; r < 4; r++) acc2[n8][r] = 0.f;

#pragma unroll
        for (int ks = 0; ks < 4; ks++) {
            uint32_t ph[4], pl[4];
            ph[0] = pack_hi2(acc[2 * ks][0],     acc[2 * ks][1]);
            ph[1] = pack_hi2(acc[2 * ks][2],     acc[2 * ks][3]);
            ph[2] = pack_hi2(acc[2 * ks + 1][0], acc[2 * ks + 1][1]);
            ph[3] = pack_hi2(acc[2 * ks + 1][2], acc[2 * ks + 1][3]);
            pl[0] = pack_lo2(acc[2 * ks][0],     acc[2 * ks][1]);
            pl[1] = pack_lo2(acc[2 * ks][2],     acc[2 * ks][3]);
            pl[2] = pack_lo2(acc[2 * ks + 1][0], acc[2 * ks + 1][1]);
            pl[3] = pack_lo2(acc[2 * ks + 1][2], acc[2 * ks + 1][3]);

            const int bcol = ks * 16 + ((quad & 1) << 3);
#pragma unroll
            for (int np = 0; np < 2; np++) {
                int brow = np * 16 + ((quad >> 1) << 3) + l8;
                uint32_t bo = (uint32_t)(brow * LV + bcol) * 2;
                uint32_t bq[4];
                ldm4(bq, uVH + bo);
                mma_bf16(acc2[2 * np + 0], ph, bq + 0);
                mma_bf16(acc2[2 * np + 1], ph, bq + 2);
                mma_bf16(acc2[2 * np + 0], pl, bq + 0);
                mma_bf16(acc2[2 * np + 1], pl, bq + 2);
                ldm4(bq, uVL + bo);
                mma_bf16(acc2[2 * np + 0], ph, bq + 0);
                mma_bf16(acc2[2 * np + 1], ph, bq + 2);
            }
        }

        // pack ctx C-frags into A-frags (hi/lo) for the proj mma
#pragma unroll
        for (int kf = 0; kf < 2; kf++) {
            cxh[it][kf * 4 + 0] = pack_hi2(acc2[2 * kf][0],     acc2[2 * kf][1]);
            cxh[it][kf * 4 + 1] = pack_hi2(acc2[2 * kf][2],     acc2[2 * kf][3]);
            cxh[it][kf * 4 + 2] = pack_hi2(acc2[2 * kf + 1][0], acc2[2 * kf + 1][1]);
            cxh[it][kf * 4 + 3] = pack_hi2(acc2[2 * kf + 1][2], acc2[2 * kf + 1][3]);
            cxl[it][kf * 4 + 0] = pack_lo2(acc2[2 * kf][0],     acc2[2 * kf][1]);
            cxl[it][kf * 4 + 1] = pack_lo2(acc2[2 * kf][2],     acc2[2 * kf][3]);
            cxl[it][kf * 4 + 2] = pack_lo2(acc2[2 * kf + 1][0], acc2[2 * kf + 1][1]);
            cxl[it][kf * 4 + 3] = pack_lo2(acc2[2 * kf + 1][2], acc2[2 * kf + 1][3]);
        }
        asm volatile("bar.sync %0, 128;" :: "r"(g + 1) : "memory");  // scratch reuse
    }

    __syncthreads();   // attn scratch dead; switch to proj layout

    // =================== proj: 4 passes of n64, k-split by group ================
    const uint32_t uWBH = sb + g * WB_GRP;
    const uint32_t uWBL = uWBH + 17408;
    float* RED = (float*)(smraw + 2 * WB_GRP);   // [64][LRED] fp32

    auto stageWB = [&](int p) {
        // rows n = p*64 .. +63, k-cols g*128 .. +127, hi+lo
#pragma unroll
        for (int rep = 0; rep < 8; rep++) {
            int idx = rep * 128 + tg;          // 0..1023
            int row = idx >> 4, cg = idx & 15;
            uint32_t so = (uint32_t)(row * LWB + cg * 8) * 2;
            size_t go = (size_t)(p * 64 + row) * 256 + g * 128 + cg * 8;
            cpasync16(uWBH + so, g_wproj_hi + go);
            cpasync16(uWBL + so, g_wproj_lo + go);
        }
        asm volatile("cp.async.commit_group;" ::: "memory");
    };

    stageWB(0);

    for (int p = 0; p < 4; p++) {
        asm volatile("cp.async.wait_group 0;" ::: "memory");
        asm volatile("bar.sync %0, 128;" :: "r"(g + 1) : "memory");

        float pacc[8][4];
#pragma unroll
        for (int n8 = 0; n8 < 8; n8++)
#pragma unroll
            for (int r = 0; r < 4; r++) pacc[n8][r] = 0.f;

#pragma unroll
        for (int it = 0; it < 4; it++) {
#pragma unroll
            for (int kf = 0; kf < 2; kf++) {
                const int bcol = it * 32 + kf * 16 + ((quad & 1) << 3);
#pragma unroll
                for (int np = 0; np < 4; np++) {
                    int brow = np * 16 + ((quad >> 1) << 3) + l8;
                    uint32_t bo = (uint32_t)(brow * LWB + bcol) * 2;
                    uint32_t bq[4];
                    ldm4(bq, uWBH + bo);
                    mma_bf16(pacc[2 * np + 0], &cxh[it][kf * 4], bq + 0);
                    mma_bf16(pacc[2 * np + 1], &cxh[it][kf * 4], bq + 2);
                    mma_bf16(pacc[2 * np + 0], &cxl[it][kf * 4], bq + 0);
                    mma_bf16(pacc[2 * np + 1], &cxl[it][kf * 4], bq + 2);
                    ldm4(bq, uWBL + bo);
                    mma_bf16(pacc[2 * np + 0], &cxh[it][kf * 4], bq + 0);
                    mma_bf16(pacc[2 * np + 1], &cxh[it][kf * 4], bq + 2);
                }
            }
        }

        // group warps done reading WB -> stage next pass under the RED barriers
        asm volatile("bar.sync %0, 128;" :: "r"(g + 1) : "memory");
        if (p + 1 < 4) stageWB(p + 1);

        // cross-group reduction: g1 writes partials, g0 adds + stores
        const int r0 = wm * 16 + (lane >> 2);
        const int c2 = (lane & 3) * 2;
        if (g == 1) {
#pragma unroll
            for (int n8 = 0; n8 < 8; n8++) {
                *(float2*)&RED[r0 * LRED + n8 * 8 + c2]       = make_float2(pacc[n8][0], pacc[n8][1]);
                *(float2*)&RED[(r0 + 8) * LRED + n8 * 8 + c2] = make_float2(pacc[n8][2], pacc[n8][3]);
            }
        }
        __syncthreads();
        if (g == 0) {
#pragma unroll
            for (int n8 = 0; n8 < 8; n8++) {
                int gc = p * 64 + n8 * 8 + c2;
                float b0 = proj_b[gc], b1 = proj_b[gc + 1];
                float2 q0 = *(const float2*)&RED[r0 * LRED + n8 * 8 + c2];
                float2 q1 = *(const float2*)&RED[(r0 + 8) * LRED + n8 * 8 + c2];
                float2 v0 = make_float2(pacc[n8][0] + q0.x + b0, pacc[n8][1] + q0.y + b1);
                float2 v1 = make_float2(pacc[n8][2] + q1.x + b0, pacc[n8][3] + q1.y + b1);
                *(float2*)&out[((size_t)win * 64 + r0) * 256 + gc]     = v0;
                *(float2*)&out[((size_t)win * 64 + r0 + 8) * 256 + gc] = v1;
            }
        }
        __syncthreads();   // RED free before next pass writes
    }
}

// ===========================================================================
extern "C" void kernel_launch(void* const* d_in, const int* in_sizes, int n_in,
                              void* d_out, int out_size)
{
    const float* x            = (const float*)d_in[0];
    const float* mask         = (const float*)d_in[1];
    const float* qkv_w        = (const float*)d_in[2];
    const float* q_bias       = (const float*)d_in[3];
    const float* v_bias       = (const float*)d_in[4];
    const float* logit_scale  = (const float*)d_in[5];
    const float* coords_table = (const float*)d_in[6];
    const float* mlp1_w       = (const float*)d_in[7];
    const float* mlp1_b       = (const float*)d_in[8];
    const float* mlp2_w       = (const float*)d_in[9];
    const float* proj_w       = (const float*)d_in[10];
    const float* proj_b       = (const float*)d_in[11];
    const int*   rel_pos_idx  = (const int*)d_in[12];
    float* out = (float*)d_out;

    cudaFuncSetAttribute(gemm_qkv_kernel,
                         cudaFuncAttributeMaxDynamicSharedMemorySize, SMEM_G);

    prep_x_kernel<<<4096, 256>>>(x);
    prep_w_kernel<<<256, 256>>>(qkv_w, proj_w, q_bias, v_bias);
    cpb_kernel<<<1, 256>>>(coords_table, mlp1_w, mlp1_b, mlp2_w, rel_pos_idx);
    gemm_qkv_kernel<<<dim3(3, 1024), 256, SMEM_G>>>();
    attnproj_kernel<<<2048, 256>>>(mask, logit_scale, proj_b, out);
}

// round 13
// speedup vs baseline: 1.0936x; 1.0936x over previous
#include <cuda_runtime.h>
#include <cuda_bf16.h>
#include <cstdint>
#include <math.h>

// ===========================================================================
// WindowAttentionV2: split-bf16 mma.sync; fused attention+proj (ctx in regs).
// B=2048 win, N=64 tok, C=256, H=8, D=32.  (R10 base + pipelined B loads)
// ===========================================================================

// ---- device scratch --------------------------------------------------------
__device__ float g_qkv[3u * 2048 * 8 * 2048];          // [(sec*2048+win)*8+h][tok*32+d]
__device__ __nv_bfloat16 g_xhi[131072u * 256];
__device__ __nv_bfloat16 g_xlo[131072u * 256];
__device__ __nv_bfloat16 g_wqkv_hi[768 * 256];         // [n][k]
__device__ __nv_bfloat16 g_wqkv_lo[768 * 256];
__device__ __nv_bfloat16 g_wproj_hi[256 * 256];
__device__ __nv_bfloat16 g_wproj_lo[256 * 256];
__device__ float g_rel_bias[8 * 64 * 64];
__device__ float g_bias_qkv[768];

// ---- helpers ----------------------------------------------------------------
__device__ __forceinline__ uint32_t smem_u32(const void* p) {
    uint32_t a;
    asm("{ .reg .u64 t; cvta.to.shared.u64 t, %1; cvt.u32.u64 %0, t; }"
        : "=r"(a) : "l"(p));
    return a;
}
__device__ __forceinline__ void mma_bf16(float* c, const uint32_t* a, const uint32_t* b) {
    asm volatile(
        "mma.sync.aligned.m16n8k16.row.col.f32.bf16.bf16.f32 "
        "{%0,%1,%2,%3}, {%4,%5,%6,%7}, {%8,%9}, {%0,%1,%2,%3};"
        : "+f"(c[0]), "+f"(c[1]), "+f"(c[2]), "+f"(c[3])
        : "r"(a[0]), "r"(a[1]), "r"(a[2]), "r"(a[3]), "r"(b[0]), "r"(b[1]));
}
__device__ __forceinline__ void ldm4(uint32_t* r, uint32_t addr) {
    asm volatile("ldmatrix.sync.aligned.m8n8.x4.shared.b16 {%0,%1,%2,%3}, [%4];"
                 : "=r"(r[0]), "=r"(r[1]), "=r"(r[2]), "=r"(r[3]) : "r"(addr));
}
__device__ __forceinline__ void cpasync16(uint32_t dst, const void* src) {
    asm volatile("cp.async.cg.shared.global [%0], [%1], 16;" :: "r"(dst), "l"(src));
}
__device__ __forceinline__ void bf_split(float v, __nv_bfloat16& hi, __nv_bfloat16& lo) {
    hi = __float2bfloat16(v);
    lo = __float2bfloat16(v - __bfloat162float(hi));
}
__device__ __forceinline__ uint32_t pack_bf(__nv_bfloat16 a, __nv_bfloat16 b) {
    return (uint32_t)__bfloat16_as_ushort(a) | ((uint32_t)__bfloat16_as_ushort(b) << 16);
}
__device__ __forceinline__ uint32_t pack_hi2(float a, float b) {
    return pack_bf(__float2bfloat16(a), __float2bfloat16(b));
}
__device__ __forceinline__ uint32_t pack_lo2(float a, float b) {
    __nv_bfloat16 ha = __float2bfloat16(a), hb = __float2bfloat16(b);
    return pack_bf(__float2bfloat16(a - __bfloat162float(ha)),
                   __float2bfloat16(b - __bfloat162float(hb)));
}

// ===========================================================================
// prep_x: x fp32 -> bf16 hi/lo
// ===========================================================================
__global__ void prep_x_kernel(const float* __restrict__ x)
{
    int gid = blockIdx.x * blockDim.x + threadIdx.x;
    int gsz = gridDim.x * blockDim.x;
    for (int i = gid; i < 131072 * 64; i += gsz) {
        float4 f = ((const float4*)x)[i];
        __nv_bfloat16 h0, h1, h2, h3, l0, l1, l2, l3;
        bf_split(f.x, h0, l0); bf_split(f.y, h1, l1);
        bf_split(f.z, h2, l2); bf_split(f.w, h3, l3);
        ((__nv_bfloat162*)g_xhi)[2 * i]     = __nv_bfloat162(h0, h1);
        ((__nv_bfloat162*)g_xhi)[2 * i + 1] = __nv_bfloat162(h2, h3);
        ((__nv_bfloat162*)g_xlo)[2 * i]     = __nv_bfloat162(l0, l1);
        ((__nv_bfloat162*)g_xlo)[2 * i + 1] = __nv_bfloat162(l2, l3);
    }
}

// ===========================================================================
// prep_w: weights -> [n][k] bf16 hi/lo, qkv bias pack
// ===========================================================================
__global__ void prep_w_kernel(const float* __restrict__ qkv_w,
                              const float* __restrict__ proj_w,
                              const float* __restrict__ q_bias,
                              const float* __restrict__ v_bias)
{
    int gid = blockIdx.x * blockDim.x + threadIdx.x;
    int gsz = gridDim.x * blockDim.x;
    for (int i = gid; i < 768 * 256; i += gsz) {
        int n = i >> 8, k = i & 255;
        __nv_bfloat16 hi, lo;
        bf_split(qkv_w[(size_t)k * 768 + n], hi, lo);
        g_wqkv_hi[i] = hi; g_wqkv_lo[i] = lo;
    }
    for (int i = gid; i < 256 * 256; i += gsz) {
        int n = i >> 8, k = i & 255;
        __nv_bfloat16 hi, lo;
        bf_split(proj_w[(size_t)k * 256 + n], hi, lo);
        g_wproj_hi[i] = hi; g_wproj_lo[i] = lo;
    }
    for (int i = gid; i < 768; i += gsz)
        g_bias_qkv[i] = (i < 256) ? q_bias[i] : ((i < 512) ? 0.f : v_bias[i - 512]);
}

// ===========================================================================
// cpb: continuous position bias (window-independent)
// ===========================================================================
__global__ void cpb_kernel(const float* __restrict__ coords_table,
                           const float* __restrict__ mlp1_w,
                           const float* __restrict__ mlp1_b,
                           const float* __restrict__ mlp2_w,
                           const int*   __restrict__ rel_pos_index)
{
    __shared__ float bt[225 * 8];
    int t = threadIdx.x;
    if (t < 225) {
        float c0 = coords_table[t * 2 + 0];
        float c1 = coords_table[t * 2 + 1];
        float acc[8];
#pragma unroll
        for (int hh = 0; hh < 8; hh++) acc[hh] = 0.f;
        for (int k = 0; k < 512; k++) {
            float hv = fmaxf(c0 * mlp1_w[k] + c1 * mlp1_w[512 + k] + mlp1_b[k], 0.f);
#pragma unroll
            for (int hh = 0; hh < 8; hh++) acc[hh] += hv * mlp2_w[k * 8 + hh];
        }
#pragma unroll
        for (int hh = 0; hh < 8; hh++) bt[t * 8 + hh] = acc[hh];
    }
    __syncthreads();
    for (int idx = t; idx < 8 * 64 * 64; idx += blockDim.x) {
        int hh = idx >> 12;
        int ij = idx & 4095;
        float v = bt[rel_pos_index[ij] * 8 + hh];
        g_rel_bias[idx] = 16.f / (1.f + __expf(-v));
    }
}

// ===========================================================================
// gemm_qkv: C[128,128] tile, split bf16, cp.async k32 double buffer.
// grid (6, 1024): ntile fastest -> A tile read once from DRAM, reused via L2.
// Inner loop: B fragments double-buffered in regs (LDSM latency hidden).
// ===========================================================================
#define LDC 40
#define CH_B  (128 * LDC * 2)         // 10240
#define BUF_B (4 * CH_B)              // AH AL BH BL = 40960
#define SMEM_G (2 * BUF_B)            // 81920

__global__ void __launch_bounds__(256, 2)
gemm_qkv_kernel()
{
    extern __shared__ __nv_bfloat16 smb[];
    const uint32_t sb = smem_u32(smb);

    const int t = threadIdx.x, lane = t & 31, w = t >> 5;
    const int wm = w & 3, wn = w >> 2;
    const int ntile = blockIdx.x, mtile = blockIdx.y;

    const size_t aoff = (size_t)mtile * 128 * 256;
    const size_t boff = (size_t)ntile * 128 * 256;

    auto stage = [&](int s, int buf) {
        const int k0 = s * 32;
        const uint32_t AH = sb + buf * BUF_B;
        const uint32_t AL = AH + CH_B;
        const uint32_t BH = AL + CH_B;
        const uint32_t BL = BH + CH_B;
#pragma unroll
        for (int rep = 0; rep < 2; rep++) {
            int idx = rep * 256 + t;
            int row = idx >> 2, cg = idx & 3;
            uint32_t so = (uint32_t)(row * LDC + cg * 8) * 2;
            size_t go = (size_t)row * 256 + k0 + cg * 8;
            cpasync16(AH + so, g_xhi + aoff + go);
            cpasync16(AL + so, g_xlo + aoff + go);
            cpasync16(BH + so, g_wqkv_hi + boff + go);
            cpasync16(BL + so, g_wqkv_lo + boff + go);
        }
        asm volatile("cp.async.commit_group;" ::: "memory");
    };

    float acc[2][8][4];
#pragma unroll
    for (int mi = 0; mi < 2; mi++)
#pragma unroll
        for (int n8 = 0; n8 < 8; n8++)
#pragma unroll
            for (int r = 0; r < 4; r++) acc[mi][n8][r] = 0.f;

    stage(0, 0);
    stage(1, 1);

    const int quad = lane >> 3, l8 = lane & 7;
    const int brow_base = wn * 64 + ((quad >> 1) << 3) + l8;

    for (int s = 0; s < 8; s++) {
        if (s < 7) asm volatile("cp.async.wait_group 1;" ::: "memory");
        else       asm volatile("cp.async.wait_group 0;" ::: "memory");
        __syncthreads();

        const uint32_t AH = sb + (s & 1) * BUF_B;
        const uint32_t AL = AH + CH_B;
        const uint32_t BH = AL + CH_B;
        const uint32_t BL = BH + CH_B;

#pragma unroll
        for (int ks = 0; ks < 2; ks++) {
            uint32_t ah[2][4], al[2][4];
            {
                int arow = wm * 32 + (lane & 15);
                int acol = ks * 16 + ((lane >> 4) << 3);
                uint32_t ao = (uint32_t)(arow * LDC + acol) * 2;
                ldm4(ah[0], AH + ao);
                ldm4(ah[1], AH + ao + 16 * LDC * 2);
                ldm4(al[0], AL + ao);
                ldm4(al[1], AL + ao + 16 * LDC * 2);
            }
            const int bcol = ks * 16 + ((quad & 1) << 3);

            // double-buffered B fragments
            uint32_t bh[2][4], bl[2][4];
            {
                uint32_t bo = (uint32_t)(brow_base * LDC + bcol) * 2;
                ldm4(bh[0], BH + bo);
                ldm4(bl[0], BL + bo);
            }
#pragma unroll
            for (int np = 0; np < 4; np++) {
                const int cur = np & 1, nxt = cur ^ 1;
                if (np < 3) {
                    uint32_t bo = (uint32_t)((brow_base + (np + 1) * 16) * LDC + bcol) * 2;
                    ldm4(bh[nxt], BH + bo);
                    ldm4(bl[nxt], BL + bo);
                }
#pragma unroll
                for (int mi = 0; mi < 2; mi++) {
                    mma_bf16(acc[mi][2 * np + 0], ah[mi], bh[cur] + 0);  // hi*whi
                    mma_bf16(acc[mi][2 * np + 1], ah[mi], bh[cur] + 2);
                    mma_bf16(acc[mi][2 * np + 0], al[mi], bh[cur] + 0);  // lo*whi
                    mma_bf16(acc[mi][2 * np + 1], al[mi], bh[cur] + 2);
                    mma_bf16(acc[mi][2 * np + 0], ah[mi], bl[cur] + 0);  // hi*wlo
                    mma_bf16(acc[mi][2 * np + 1], ah[mi], bl[cur] + 2);
                }
            }
        }
        __syncthreads();
        if (s + 2 < 8) stage(s + 2, s & 1);
    }

    // ---- epilogue: scatter to g_qkv + bias --------------------------------------
    const int row_l = wm * 32 + (lane >> 2);
    const int col_l = wn * 64 + (lane & 3) * 2;
#pragma unroll
    for (int mi = 0; mi < 2; mi++) {
#pragma unroll
        for (int n8 = 0; n8 < 8; n8++) {
            int gc = ntile * 128 + col_l + n8 * 8;
            int sec = gc >> 8, hh = (gc >> 5) & 7, d = gc & 31;
            float b0 = g_bias_qkv[gc], b1 = g_bias_qkv[gc + 1];
#pragma unroll
            for (int half = 0; half < 2; half++) {
                int row = mtile * 128 + row_l + mi * 16 + half * 8;
                int win = row >> 6, tok = row & 63;
                size_t addr = (((size_t)sec * 2048 + win) * 8 + hh) * 2048
                              + (size_t)tok * 32 + d;
                float2 v;
                v.x = acc[mi][n8][2 * half + 0] + b0;
                v.y = acc[mi][n8][2 * half + 1] + b1;
                *(float2*)&g_qkv[addr] = v;
            }
        }
    }
}

// ===========================================================================
// attnproj: fused attention + proj. CTA = window, 256 thr = 2 groups x 4 warps.
// (identical to the R10 version)
// ===========================================================================
#define LQ 40    // q/k hi/lo row stride (bf16)
#define LV 72    // VT row stride (bf16)
#define LWB 136  // proj B stage row stride (bf16): 272B % 128 == 16
#define LRED 36

#define GRP_BYTES 29696

__global__ void __launch_bounds__(256, 2)
attnproj_kernel(const float* __restrict__ mask,
                const float* __restrict__ logit_scale,
                const float* __restrict__ proj_b,
                float*       __restrict__ out)
{
    __shared__ __align__(16) char smraw[2 * GRP_BYTES];
    const uint32_t sb = smem_u32(smraw);

    const int t = threadIdx.x, lane = t & 31, w = t >> 5;
    const int g = w >> 2, wm = w & 3, tg = t & 127;
    const int win = blockIdx.x;
    const int quad = lane >> 3, l8 = lane & 7;

    const uint32_t gb = sb + g * GRP_BYTES;
    const uint32_t uQH = gb, uQL = gb + 5120, uKH = gb + 10240, uKL = gb + 15360;
    const uint32_t uVH = gb + 20480, uVL = gb + 25088;
    __nv_bfloat16* VTH = (__nv_bfloat16*)(smraw + g * GRP_BYTES + 20480);
    __nv_bfloat16* VTL = (__nv_bfloat16*)(smraw + g * GRP_BYTES + 25088);

    uint32_t cxh[4][8], cxl[4][8];

    for (int it = 0; it < 4; it++) {
        const int h = g * 4 + it;
        const float* qg = g_qkv + (((size_t)0 * 2048 + win) * 8 + h) * 2048;
        const float* kg = g_qkv + (((size_t)1 * 2048 + win) * 8 + h) * 2048;
        const float* vg = g_qkv + (((size_t)2 * 2048 + win) * 8 + h) * 2048;

#pragma unroll
        for (int rep = 0; rep < 4; rep++) {
            int idx = rep * 128 + tg;
            int tok = idx >> 3, d4 = (idx & 7) * 4;
            float4 fv = *(const float4*)(vg + idx * 4);
            float vv[4] = {fv.x, fv.y, fv.z, fv.w};
#pragma unroll
            for (int j = 0; j < 4; j++) {
                __nv_bfloat16 hi, lo;
                bf_split(vv[j], hi, lo);
                VTH[(d4 + j) * LV + tok] = hi;
                VTL[(d4 + j) * LV + tok] = lo;
            }
        }

        {
            int r = tg & 63;
            const float* src = (tg < 64) ? (qg + r * 32) : (kg + r * 32);
            float4 rv[8];
            float s = 0.f;
#pragma unroll
            for (int i = 0; i < 8; i++) {
                rv[i] = *(const float4*)(src + i * 4);
                s += rv[i].x * rv[i].x + rv[i].y * rv[i].y
                   + rv[i].z * rv[i].z + rv[i].w * rv[i].w;
            }
            float inv = rsqrtf(fmaxf(s, 1e-24f));
            if (tg < 64) inv *= __expf(fminf(logit_scale[h], 4.605170185988092f));
            uint32_t dh = ((tg < 64) ? uQH : uKH) + (uint32_t)(r * LQ) * 2;
            uint32_t dl = ((tg < 64) ? uQL : uKL) + (uint32_t)(r * LQ) * 2;
#pragma unroll
            for (int i = 0; i < 8; i++) {
                float v0 = rv[i].x * inv, v1 = rv[i].y * inv;
                float v2 = rv[i].z * inv, v3 = rv[i].w * inv;
                asm volatile("st.shared.v2.b32 [%0], {%1,%2};"
                             :: "r"(dh + i * 8), "r"(pack_hi2(v0, v1)), "r"(pack_hi2(v2, v3)));
                asm volatile("st.shared.v2.b32 [%0], {%1,%2};"
                             :: "r"(dl + i * 8), "r"(pack_lo2(v0, v1)), "r"(pack_lo2(v2, v3)));
            }
        }
        asm volatile("bar.sync %0, 128;" :: "r"(g + 1) : "memory");

        float acc[8][4];
#pragma unroll
        for (int n8 = 0; n8 < 8; n8++)
#pragma unroll
            for (int r = 0; r < 4; r++) acc[n8][r] = 0.f;

#pragma unroll
        for (int ks = 0; ks < 2; ks++) {
            uint32_t ah[4], al[4];
            {
                int arow = wm * 16 + (lane & 15);
                int acol = ks * 16 + ((lane >> 4) << 3);
                uint32_t ao = (uint32_t)(arow * LQ + acol) * 2;
                ldm4(ah, uQH + ao);
                ldm4(al, uQL + ao);
            }
            const int bcol = ks * 16 + ((quad & 1) << 3);
#pragma unroll
            for (int np = 0; np < 4; np++) {
                int brow = np * 16 + ((quad >> 1) << 3) + l8;
                uint32_t bo = (uint32_t)(brow * LQ + bcol) * 2;
                uint32_t bq[4];
                ldm4(bq, uKH + bo);
                mma_bf16(acc[2 * np + 0], ah, bq + 0);
                mma_bf16(acc[2 * np + 1], ah, bq + 2);
                mma_bf16(acc[2 * np + 0], al, bq + 0);
                mma_bf16(acc[2 * np + 1], al, bq + 2);
                ldm4(bq, uKL + bo);
                mma_bf16(acc[2 * np + 0], ah, bq + 0);
                mma_bf16(acc[2 * np + 1], ah, bq + 2);
            }
        }

        {
            const float* rb = g_rel_bias + h * 4096;
            const float* mk = mask + (size_t)(win & 255) * 4096;
            const int i0 = wm * 16 + (lane >> 2);
            const int i1 = i0 + 8;
            const int jc = (lane & 3) * 2;
#pragma unroll
            for (int n8 = 0; n8 < 8; n8++) {
                int o0 = i0 * 64 + n8 * 8 + jc;
                int o1 = i1 * 64 + n8 * 8 + jc;
                float2 r0 = *(const float2*)(rb + o0), m0 = *(const float2*)(mk + o0);
                float2 r1 = *(const float2*)(rb + o1), m1 = *(const float2*)(mk + o1);
                acc[n8][0] += r0.x + m0.x;  acc[n8][1] += r0.y + m0.y;
                acc[n8][2] += r1.x + m1.x;  acc[n8][3] += r1.y + m1.y;
            }
            float mx0 = -1e30f, mx1 = -1e30f;
#pragma unroll
            for (int n8 = 0; n8 < 8; n8++) {
                mx0 = fmaxf(mx0, fmaxf(acc[n8][0], acc[n8][1]));
                mx1 = fmaxf(mx1, fmaxf(acc[n8][2], acc[n8][3]));
            }
            mx0 = fmaxf(mx0, __shfl_xor_sync(0xffffffffu, mx0, 1));
            mx0 = fmaxf(mx0, __shfl_xor_sync(0xffffffffu, mx0, 2));
            mx1 = fmaxf(mx1, __shfl_xor_sync(0xffffffffu, mx1, 1));
            mx1 = fmaxf(mx1, __shfl_xor_sync(0xffffffffu, mx1, 2));
            float s0 = 0.f, s1 = 0.f;
#pragma unroll
            for (int n8 = 0; n8 < 8; n8++) {
                acc[n8][0] = __expf(acc[n8][0] - mx0);
                acc[n8][1] = __expf(acc[n8][1] - mx0);
                acc[n8][2] = __expf(acc[n8][2] - mx1);
                acc[n8][3] = __expf(acc[n8][3] - mx1);
                s0 += acc[n8][0] + acc[n8][1];
                s1 += acc[n8][2] + acc[n8][3];
            }
            s0 += __shfl_xor_sync(0xffffffffu, s0, 1);
            s0 += __shfl_xor_sync(0xffffffffu, s0, 2);
            s1 += __shfl_xor_sync(0xffffffffu, s1, 1);
            s1 += __shfl_xor_sync(0xffffffffu, s1, 2);
            float inv0 = 1.f / s0, inv1 = 1.f / s1;
#pragma unroll
            for (int n8 = 0; n8 < 8; n8++) {
                acc[n8][0] *= inv0;  acc[n8][1] *= inv0;
                acc[n8][2] *= inv1;  acc[n8][3] *= inv1;
            }
        }

        float acc2[4][4];
#pragma unroll
        for (int n8 = 0; n8 < 4; n8++)
#pragma unroll
            for (int r = 0; r < 4; r++) acc2[n8][r] = 0.f;

#pragma unroll
        for (int ks = 0; ks < 4; ks++) {
            uint32_t ph[4], pl[4];
            ph[0] = pack_hi2(acc[2 * ks][0],     acc[2 * ks][1]);
            ph[1] = pack_hi2(acc[2 * ks][2],     acc[2 * ks][3]);
            ph[2] = pack_hi2(acc[2 * ks + 1][0], acc[2 * ks + 1][1]);
            ph[3] = pack_hi2(acc[2 * ks + 1][2], acc[2 * ks + 1][3]);
            pl[0] = pack_lo2(acc[2 * ks][0],     acc[2 * ks][1]);
            pl[1] = pack_lo2(acc[2 * ks][2],     acc[2 * ks][3]);
            pl[2] = pack_lo2(acc[2 * ks + 1][0], acc[2 * ks + 1][1]);
            pl[3] = pack_lo2(acc[2 * ks + 1][2], acc[2 * ks + 1][3]);

            const int bcol = ks * 16 + ((quad & 1) << 3);
#pragma unroll
            for (int np = 0; np < 2; np++) {
                int brow = np * 16 + ((quad >> 1) << 3) + l8;
                uint32_t bo = (uint32_t)(brow * LV + bcol) * 2;
                uint32_t bq[4];
                ldm4(bq, uVH + bo);
                mma_bf16(acc2[2 * np + 0], ph, bq + 0);
                mma_bf16(acc2[2 * np + 1], ph, bq + 2);
                mma_bf16(acc2[2 * np + 0], pl, bq + 0);
                mma_bf16(acc2[2 * np + 1], pl, bq + 2);
                ldm4(bq, uVL + bo);
                mma_bf16(acc2[2 * np + 0], ph, bq + 0);
                mma_bf16(acc2[2 * np + 1], ph, bq + 2);
            }
        }

#pragma unroll
        for (int kf = 0; kf < 2; kf++) {
            cxh[it][kf * 4 + 0] = pack_hi2(acc2[2 * kf][0],     acc2[2 * kf][1]);
            cxh[it][kf * 4 + 1] = pack_hi2(acc2[2 * kf][2],     acc2[2 * kf][3]);
            cxh[it][kf * 4 + 2] = pack_hi2(acc2[2 * kf + 1][0], acc2[2 * kf + 1][1]);
            cxh[it][kf * 4 + 3] = pack_hi2(acc2[2 * kf + 1][2], acc2[2 * kf + 1][3]);
            cxl[it][kf * 4 + 0] = pack_lo2(acc2[2 * kf][0],     acc2[2 * kf][1]);
            cxl[it][kf * 4 + 1] = pack_lo2(acc2[2 * kf][2],     acc2[2 * kf][3]);
            cxl[it][kf * 4 + 2] = pack_lo2(acc2[2 * kf + 1][0], acc2[2 * kf + 1][1]);
            cxl[it][kf * 4 + 3] = pack_lo2(acc2[2 * kf + 1][2], acc2[2 * kf + 1][3]);
        }
        asm volatile("bar.sync %0, 128;" :: "r"(g + 1) : "memory");
    }

    __syncthreads();

    // =================== proj: 8 passes of n32, k-split by group ================
    const uint32_t uWBH = sb + g * 17408;
    const uint32_t uWBL = uWBH + 8704;
    float* RED = (float*)(smraw + 2 * 17408);

    for (int p = 0; p < 8; p++) {
#pragma unroll
        for (int rep = 0; rep < 4; rep++) {
            int idx = rep * 128 + tg;
            int row = idx >> 4, cg = idx & 15;
            uint32_t so = (uint32_t)(row * LWB + cg * 8) * 2;
            size_t go = (size_t)(p * 32 + row) * 256 + g * 128 + cg * 8;
            cpasync16(uWBH + so, g_wproj_hi + go);
            cpasync16(uWBL + so, g_wproj_lo + go);
        }
        asm volatile("cp.async.commit_group;" ::: "memory");
        asm volatile("cp.async.wait_group 0;" ::: "memory");
        asm volatile("bar.sync %0, 128;" :: "r"(g + 1) : "memory");

        float pacc[4][4];
#pragma unroll
        for (int n8 = 0; n8 < 4; n8++)
#pragma unroll
            for (int r = 0; r < 4; r++) pacc[n8][r] = 0.f;

#pragma unroll
        for (int it = 0; it < 4; it++) {
#pragma unroll
            for (int kf = 0; kf < 2; kf++) {
                const int bcol = it * 32 + kf * 16 + ((quad & 1) << 3);
#pragma unroll
                for (int np = 0; np < 2; np++) {
                    int brow = np * 16 + ((quad >> 1) << 3) + l8;
                    uint32_t bo = (uint32_t)(brow * LWB + bcol) * 2;
                    uint32_t bq[4];
                    ldm4(bq, uWBH + bo);
                    mma_bf16(pacc[2 * np + 0], &cxh[it][kf * 4], bq + 0);
                    mma_bf16(pacc[2 * np + 1], &cxh[it][kf * 4], bq + 2);
                    mma_bf16(pacc[2 * np + 0], &cxl[it][kf * 4], bq + 0);
                    mma_bf16(pacc[2 * np + 1], &cxl[it][kf * 4], bq + 2);
                    ldm4(bq, uWBL + bo);
                    mma_bf16(pacc[2 * np + 0], &cxh[it][kf * 4], bq + 0);
                    mma_bf16(pacc[2 * np + 1], &cxh[it][kf * 4], bq + 2);
                }
            }
        }

        const int r0 = wm * 16 + (lane >> 2);
        const int c2 = (lane & 3) * 2;
        if (g == 1) {
#pragma unroll
            for (int n8 = 0; n8 < 4; n8++) {
                *(float2*)&RED[r0 * LRED + n8 * 8 + c2]       = make_float2(pacc[n8][0], pacc[n8][1]);
                *(float2*)&RED[(r0 + 8) * LRED + n8 * 8 + c2] = make_float2(pacc[n8][2], pacc[n8][3]);
            }
        }
        __syncthreads();
        if (g == 0) {
#pragma unroll
            for (int n8 = 0; n8 < 4; n8++) {
                int gc = p * 32 + n8 * 8 + c2;
                float b0 = proj_b[gc], b1 = proj_b[gc + 1];
                float2 q0 = *(const float2*)&RED[r0 * LRED + n8 * 8 + c2];
                float2 q1 = *(const float2*)&RED[(r0 + 8) * LRED + n8 * 8 + c2];
                float2 v0 = make_float2(pacc[n8][0] + q0.x + b0, pacc[n8][1] + q0.y + b1);
                float2 v1 = make_float2(pacc[n8][2] + q1.x + b0, pacc[n8][3] + q1.y + b1);
                *(float2*)&out[((size_t)win * 64 + r0) * 256 + gc]     = v0;
                *(float2*)&out[((size_t)win * 64 + r0 + 8) * 256 + gc] = v1;
            }
        }
        __syncthreads();
    }
}

// ===========================================================================
extern "C" void kernel_launch(void* const* d_in, const int* in_sizes, int n_in,
                              void* d_out, int out_size)
{
    const float* x            = (const float*)d_in[0];
    const float* mask         = (const float*)d_in[1];
    const float* qkv_w        = (const float*)d_in[2];
    const float* q_bias       = (const float*)d_in[3];
    const float* v_bias       = (const float*)d_in[4];
    const float* logit_scale  = (const float*)d_in[5];
    const float* coords_table = (const float*)d_in[6];
    const float* mlp1_w       = (const float*)d_in[7];
    const float* mlp1_b       = (const float*)d_in[8];
    const float* mlp2_w       = (const float*)d_in[9];
    const float* proj_w       = (const float*)d_in[10];
    const float* proj_b       = (const float*)d_in[11];
    const int*   rel_pos_idx  = (const int*)d_in[12];
    float* out = (float*)d_out;

    cudaFuncSetAttribute(gemm_qkv_kernel,
                         cudaFuncAttributeMaxDynamicSharedMemorySize, SMEM_G);

    prep_x_kernel<<<4096, 256>>>(x);
    prep_w_kernel<<<256, 256>>>(qkv_w, proj_w, q_bias, v_bias);
    cpb_kernel<<<1, 256>>>(coords_table, mlp1_w, mlp1_b, mlp2_w, rel_pos_idx);
    gemm_qkv_kernel<<<dim3(6, 1024), 256, SMEM_G>>>();
    attnproj_kernel<<<2048, 256>>>(mask, logit_scale, proj_b, out);
}